// round 6
// baseline (speedup 1.0000x reference)
#include <cuda_runtime.h>
#include <cuda_fp16.h>

#define NN 50000
#define EE 1600000
#define SCAN_B 256
#define NBLK ((NN + SCAN_B - 1) / SCAN_B)   // 196

// Scratch (device globals; no allocations allowed)
__device__ __align__(16) float4 g_h [NN * 32];     // h = (1+eps)*x + agg
__device__ __align__(16) float4 g_h1[NN * 32];     // h @ W1 + b1
__device__ float g_sum[128];
__device__ float g_sumsq[128];
__device__ __align__(16) float g_combo[125 * 128]; // all 5^3 bond-emb sums
__device__ __align__(16) uint2 g_xh[NN * 32];      // x in fp16: [node][32] x uint2(4 vals)
__device__ int  g_deg[NN];
__device__ int  g_off[NN];
__device__ int  g_cur[NN];
__device__ int  g_bsum[NBLK];
__device__ int  g_boff[NBLK];
__device__ __align__(16) int2 g_csr[EE];           // {src, combo_code} grouped by dst

// ---------------------------------------------------------------------------
__global__ void zero_kernel() {
    int i = blockIdx.x * blockDim.x + threadIdx.x;
    if (i < NN) g_deg[i] = 0;
    if (i < 128) { g_sum[i] = 0.f; g_sumsq[i] = 0.f; }
}

// Convert x -> fp16 (for the gather path only; 10 mantissa bits)
__global__ void convert_kernel(const float4* __restrict__ x4) {
    int i = blockIdx.x * blockDim.x + threadIdx.x;
    if (i >= NN * 32) return;
    float4 v = x4[i];
    __half2 lo = __float22half2_rn(make_float2(v.x, v.y));
    __half2 hi = __float22half2_rn(make_float2(v.z, v.w));
    uint2 p;
    p.x = *(unsigned*)&lo;
    p.y = *(unsigned*)&hi;
    g_xh[i] = p;
}

__global__ void combo_kernel(const float* __restrict__ be) {
    int c = blockIdx.x, t = threadIdx.x;
    g_combo[c * 128 + t] = be[(c / 25) * 128 + t]
                         + be[(5 + (c / 5) % 5) * 128 + t]
                         + be[(10 + c % 5) * 128 + t];
}

__global__ void hist_kernel(const int* __restrict__ dst) {
    int e = blockIdx.x * blockDim.x + threadIdx.x;
    if (e < EE) atomicAdd(&g_deg[dst[e]], 1);
}

// ---- Chip-wide 3-stage exclusive scan of g_deg -> g_off / g_cur ----------
__global__ void blocksum_kernel() {
    __shared__ int ws[8];
    int i = blockIdx.x * SCAN_B + threadIdx.x;
    int v = (i < NN) ? g_deg[i] : 0;
#pragma unroll
    for (int o = 16; o > 0; o >>= 1) v += __shfl_down_sync(0xffffffffu, v, o);
    if ((threadIdx.x & 31) == 0) ws[threadIdx.x >> 5] = v;
    __syncthreads();
    if (threadIdx.x < 8) {
        int s = ws[threadIdx.x];
#pragma unroll
        for (int o = 4; o > 0; o >>= 1) s += __shfl_down_sync(0xffu, s, o);
        if (threadIdx.x == 0) g_bsum[blockIdx.x] = s;
    }
}

__global__ void bscan_kernel() {
    __shared__ int sh[SCAN_B];
    int t = threadIdx.x;
    int v = (t < NBLK) ? g_bsum[t] : 0;
    sh[t] = v;
    __syncthreads();
    for (int o = 1; o < SCAN_B; o <<= 1) {
        int u = (t >= o) ? sh[t - o] : 0;
        __syncthreads();
        sh[t] += u;
        __syncthreads();
    }
    if (t < NBLK) g_boff[t] = sh[t] - v;   // exclusive
}

__global__ void offsets_kernel() {
    __shared__ int ws[8];
    int t = threadIdx.x, lane = t & 31, w = t >> 5;
    int i = blockIdx.x * SCAN_B + t;
    int v = (i < NN) ? g_deg[i] : 0;
    int s = v;
#pragma unroll
    for (int o = 1; o < 32; o <<= 1) {
        int u = __shfl_up_sync(0xffffffffu, s, o);
        if (lane >= o) s += u;
    }
    if (lane == 31) ws[w] = s;
    __syncthreads();
    if (t < 8) {
        int a = ws[t];
#pragma unroll
        for (int o = 1; o < 8; o <<= 1) {
            int u = __shfl_up_sync(0xffu, a, o);
            if (t >= o) a += u;
        }
        ws[t] = a;
    }
    __syncthreads();
    int ex = s - v + (w ? ws[w - 1] : 0) + g_boff[blockIdx.x];
    if (i < NN) { g_off[i] = ex; g_cur[i] = ex; }
}

__global__ void scatter_kernel(const int* __restrict__ src,
                               const int* __restrict__ dst,
                               const int* __restrict__ ea) {
    int e = blockIdx.x * blockDim.x + threadIdx.x;
    if (e >= EE) return;
    int d = dst[e];
    int code = (ea[e * 3 + 0] * 5 + ea[e * 3 + 1]) * 5 + ea[e * 3 + 2];
    int pos = atomicAdd(&g_cur[d], 1);
    g_csr[pos] = make_int2(src[e], code);
}

// ---------------------------------------------------------------------------
// Aggregation: one warp per dst node. fp16 gather of x[src] (half traffic),
// fp32 math, register accumulation, single write.
// ---------------------------------------------------------------------------
__device__ __forceinline__ void acc_edge(float4& acc, int2 a, int lane,
                                         const float4* cb4) {
    uint2 p = g_xh[a.x * 32 + lane];
    float2 lo = __half22float2(*(__half2*)&p.x);
    float2 hi = __half22float2(*(__half2*)&p.y);
    float4 ca = cb4[a.y * 32 + lane];
    acc.x += fmaxf(lo.x + ca.x, 0.f);
    acc.y += fmaxf(lo.y + ca.y, 0.f);
    acc.z += fmaxf(hi.x + ca.z, 0.f);
    acc.w += fmaxf(hi.y + ca.w, 0.f);
}

__global__ void agg_kernel(const float4* __restrict__ x4,
                           const float*  __restrict__ eps) {
    int gt = blockIdx.x * blockDim.x + threadIdx.x;
    int v = gt >> 5;
    if (v >= NN) return;
    int lane = gt & 31;

    const float4* cb4 = (const float4*)g_combo;
    int start = g_off[v];
    int deg   = g_deg[v];

    float4 acc = make_float4(0, 0, 0, 0);
    int i = 0;
    for (; i + 4 <= deg; i += 4) {
        int2 a = g_csr[start + i];
        int2 b = g_csr[start + i + 1];
        int2 c = g_csr[start + i + 2];
        int2 d = g_csr[start + i + 3];
        acc_edge(acc, a, lane, cb4);
        acc_edge(acc, b, lane, cb4);
        acc_edge(acc, c, lane, cb4);
        acc_edge(acc, d, lane, cb4);
    }
    for (; i < deg; i++) acc_edge(acc, g_csr[start + i], lane, cb4);

    float c = 1.0f + *eps;
    float4 xv = x4[v * 32 + lane];
    float4 h;
    h.x = fmaf(c, xv.x, acc.x);
    h.y = fmaf(c, xv.y, acc.y);
    h.z = fmaf(c, xv.z, acc.z);
    h.w = fmaf(c, xv.w, acc.w);
    g_h[v * 32 + lane] = h;
}

// ---------------------------------------------------------------------------
// GEMM via fma.rn.f32x2, even/odd-k packed accumulators (unchanged).
// ---------------------------------------------------------------------------
#define WT_PITCH 132
#define WT_FLOATS (128 * WT_PITCH)
#define XS_OFF_B  (WT_FLOATS * 4)
#define GEMM_SMEM (XS_OFF_B + 64 * 128 * 4)

__device__ __forceinline__ float2 unpk(unsigned long long v) {
    float2 r;
    asm("mov.b64 {%0, %1}, %2;" : "=f"(r.x), "=f"(r.y) : "l"(v));
    return r;
}

template <int PASS>
__global__ __launch_bounds__(128)
void gemm_kernel(const float* __restrict__ Wg,
                 const float* __restrict__ bias,
                 float*       __restrict__ outp,
                 const float* __restrict__ gamma,
                 const float* __restrict__ beta) {
    extern __shared__ float sh[];
    __shared__ __align__(16) float ssum[128];
    __shared__ __align__(16) float ssq[128];
    __shared__ __align__(16) float sa[128];
    __shared__ __align__(16) float sb[128];

    const int t    = threadIdx.x;
    const int lane = t & 31;
    const int wrp  = t >> 5;

    if (PASS == 1) { ssum[t] = 0.f; ssq[t] = 0.f; }
    if (PASS == 2) {
        const float inv = 1.0f / (float)NN;
        float mean = g_sum[t] * inv;
        float var  = g_sumsq[t] * inv - mean * mean;
        float s = gamma[t] * rsqrtf(var + 1e-5f);
        sa[t] = s;
        sb[t] = beta[t] - mean * s;
    }
    __syncthreads();

    // Stage W transposed: Wt[c][k] = W[k][c], pitch 132
    {
        const int c = t;
        for (int g = 0; g < 32; g++) {
            int k0 = g * 4;
            float w0 = Wg[(k0 + 0) * 128 + c];
            float w1 = Wg[(k0 + 1) * 128 + c];
            float w2 = Wg[(k0 + 2) * 128 + c];
            float w3 = Wg[(k0 + 3) * 128 + c];
            *(float4*)&sh[c * WT_PITCH + k0] = make_float4(w0, w1, w2, w3);
        }
    }

    const float4* in4 = (PASS == 1) ? (const float4*)g_h : (const float4*)g_h1;
    float* xs = sh + WT_FLOATS;
    const int rowbase = blockIdx.x * 64;
#pragma unroll
    for (int j = 0; j < 16; j++) {
        int p = t + j * 128;
        int row = p >> 5, cp = p & 31;
        int gr = rowbase + row;
        float4 v = make_float4(0, 0, 0, 0);
        if (gr < NN) v = in4[gr * 32 + cp];
        if (PASS == 2) {
            float4 a = *(const float4*)&sa[cp * 4];
            float4 b = *(const float4*)&sb[cp * 4];
            v.x = fmaxf(fmaf(v.x, a.x, b.x), 0.f);
            v.y = fmaxf(fmaf(v.y, a.y, b.y), 0.f);
            v.z = fmaxf(fmaf(v.z, a.z, b.z), 0.f);
            v.w = fmaxf(fmaf(v.w, a.w, b.w), 0.f);
        }
        *(float4*)&xs[row * 128 + cp * 4] = v;
    }
    __syncthreads();

    float* out_f = (PASS == 1) ? (float*)g_h1 : outp;

    float bv[4];
#pragma unroll
    for (int cc = 0; cc < 4; cc++) bv[cc] = bias[lane + 32 * cc];

    const unsigned shb = (unsigned)__cvta_generic_to_shared(sh);
    unsigned wb[4];
#pragma unroll
    for (int cc = 0; cc < 4; cc++) wb[cc] = shb + (unsigned)((lane + 32 * cc) * WT_PITCH) * 4u;
    const unsigned xsb = shb + XS_OFF_B;

    float ts[4] = {0, 0, 0, 0};
    float tq[4] = {0, 0, 0, 0};

    for (int half = 0; half < 2; half++) {
        const int r0 = half * 32 + wrp * 8;
        unsigned xr[8];
#pragma unroll
        for (int r = 0; r < 8; r++) xr[r] = xsb + (unsigned)((r0 + r) * 128) * 4u;

        unsigned long long acc[8][4];
#pragma unroll
        for (int r = 0; r < 8; r++)
#pragma unroll
            for (int cc = 0; cc < 4; cc++) acc[r][cc] = 0ULL;

#pragma unroll 4
        for (int k = 0; k < 128; k += 4) {
            unsigned long long w01[4], w23[4];
#pragma unroll
            for (int cc = 0; cc < 4; cc++)
                asm("ld.shared.v2.b64 {%0, %1}, [%2];"
                    : "=l"(w01[cc]), "=l"(w23[cc]) : "r"(wb[cc] + (unsigned)(k * 4)));
#pragma unroll
            for (int r = 0; r < 8; r++) {
                unsigned long long x01, x23;
                asm("ld.shared.v2.b64 {%0, %1}, [%2];"
                    : "=l"(x01), "=l"(x23) : "r"(xr[r] + (unsigned)(k * 4)));
#pragma unroll
                for (int cc = 0; cc < 4; cc++) {
                    asm("fma.rn.f32x2 %0, %1, %2, %0;" : "+l"(acc[r][cc]) : "l"(x01), "l"(w01[cc]));
                    asm("fma.rn.f32x2 %0, %1, %2, %0;" : "+l"(acc[r][cc]) : "l"(x23), "l"(w23[cc]));
                }
            }
        }

#pragma unroll
        for (int r = 0; r < 8; r++) {
            int gr = rowbase + r0 + r;
            if (gr < NN) {
#pragma unroll
                for (int cc = 0; cc < 4; cc++) {
                    float2 p = unpk(acc[r][cc]);
                    float o = p.x + p.y + bv[cc];
                    out_f[gr * 128 + lane + 32 * cc] = o;
                    if (PASS == 1) { ts[cc] += o; tq[cc] += o * o; }
                }
            }
        }
    }

    if (PASS == 1) {
#pragma unroll
        for (int cc = 0; cc < 4; cc++) {
            atomicAdd(&ssum[lane + 32 * cc], ts[cc]);
            atomicAdd(&ssq [lane + 32 * cc], tq[cc]);
        }
        __syncthreads();
        atomicAdd(&g_sum[t],   ssum[t]);
        atomicAdd(&g_sumsq[t], ssq[t]);
    }
}

// ---------------------------------------------------------------------------
extern "C" void kernel_launch(void* const* d_in, const int* in_sizes, int n_in,
                              void* d_out, int out_size) {
    const float* x     = (const float*)d_in[0];
    const int*   ea    = (const int*)  d_in[1];
    const int*   src   = (const int*)  d_in[2];
    const int*   dst   = (const int*)  d_in[3];
    const float* bond  = (const float*)d_in[4];
    const float* eps   = (const float*)d_in[5];
    const float* W1    = (const float*)d_in[6];
    const float* b1    = (const float*)d_in[7];
    const float* gamma = (const float*)d_in[8];
    const float* beta  = (const float*)d_in[9];
    const float* W2    = (const float*)d_in[10];
    const float* b2    = (const float*)d_in[11];

    cudaFuncSetAttribute(gemm_kernel<1>, cudaFuncAttributeMaxDynamicSharedMemorySize, GEMM_SMEM);
    cudaFuncSetAttribute(gemm_kernel<2>, cudaFuncAttributeMaxDynamicSharedMemorySize, GEMM_SMEM);

    zero_kernel<<<(NN + 255) / 256, 256>>>();
    convert_kernel<<<(NN * 32 + 255) / 256, 256>>>((const float4*)x);
    combo_kernel<<<125, 128>>>(bond);
    hist_kernel<<<(EE + 255) / 256, 256>>>(dst);
    blocksum_kernel<<<NBLK, SCAN_B>>>();
    bscan_kernel<<<1, SCAN_B>>>();
    offsets_kernel<<<NBLK, SCAN_B>>>();
    scatter_kernel<<<(EE + 255) / 256, 256>>>(src, dst, ea);
    agg_kernel<<<(NN * 32 + 255) / 256, 256>>>((const float4*)x, eps);
    gemm_kernel<1><<<(NN + 63) / 64, 128, GEMM_SMEM>>>(W1, b1, nullptr, nullptr, nullptr);
    gemm_kernel<2><<<(NN + 63) / 64, 128, GEMM_SMEM>>>(W2, b2, (float*)d_out, gamma, beta);
}

// round 7
// speedup vs baseline: 1.4883x; 1.4883x over previous
#include <cuda_runtime.h>
#include <cuda_fp16.h>

#define NN 50000
#define EE 1600000
#define SCAN_B 256
#define NBLK ((NN + SCAN_B - 1) / SCAN_B)   // 196

// Scratch (device globals; no allocations allowed)
__device__ __align__(16) float4 g_h [NN * 32];     // h = (1+eps)*x + agg
__device__ __align__(16) float4 g_h1[NN * 32];     // h @ W1 + b1
__device__ float g_sum[128];
__device__ float g_sumsq[128];
__device__ __align__(16) float g_combo[125 * 128]; // all 5^3 bond-emb sums
__device__ __align__(16) uint2 g_xh[NN * 32];      // x in fp16
__device__ int  g_deg[NN];
__device__ int  g_off[NN];
__device__ int  g_cur[NN];
__device__ int  g_bsum[NBLK];
__device__ int  g_boff[NBLK];
__device__ int  g_csr[EE];                         // packed (src<<7)|code, grouped by dst

// ---------------------------------------------------------------------------
// Setup: zero deg/stats + convert x -> fp16
// ---------------------------------------------------------------------------
__global__ void setup_kernel(const float4* __restrict__ x4) {
    int i = blockIdx.x * blockDim.x + threadIdx.x;
    if (i < NN) g_deg[i] = 0;
    if (i < 128) { g_sum[i] = 0.f; g_sumsq[i] = 0.f; }
    if (i < NN * 32) {
        float4 v = x4[i];
        __half2 lo = __float22half2_rn(make_float2(v.x, v.y));
        __half2 hi = __float22half2_rn(make_float2(v.z, v.w));
        uint2 p;
        p.x = *(unsigned*)&lo;
        p.y = *(unsigned*)&hi;
        g_xh[i] = p;
    }
}

__global__ void combo_kernel(const float* __restrict__ be) {
    int c = blockIdx.x, t = threadIdx.x;
    g_combo[c * 128 + t] = be[(c / 25) * 128 + t]
                         + be[(5 + (c / 5) % 5) * 128 + t]
                         + be[(10 + c % 5) * 128 + t];
}

__global__ void hist_kernel(const int* __restrict__ dst) {
    int e = blockIdx.x * blockDim.x + threadIdx.x;
    if (e < EE) atomicAdd(&g_deg[dst[e]], 1);
}

// ---- Chip-wide 3-stage exclusive scan of g_deg -> g_off / g_cur ----------
__global__ void blocksum_kernel() {
    __shared__ int ws[8];
    int i = blockIdx.x * SCAN_B + threadIdx.x;
    int v = (i < NN) ? g_deg[i] : 0;
#pragma unroll
    for (int o = 16; o > 0; o >>= 1) v += __shfl_down_sync(0xffffffffu, v, o);
    if ((threadIdx.x & 31) == 0) ws[threadIdx.x >> 5] = v;
    __syncthreads();
    if (threadIdx.x < 8) {
        int s = ws[threadIdx.x];
#pragma unroll
        for (int o = 4; o > 0; o >>= 1) s += __shfl_down_sync(0xffu, s, o);
        if (threadIdx.x == 0) g_bsum[blockIdx.x] = s;
    }
}

__global__ void bscan_kernel() {
    __shared__ int sh[SCAN_B];
    int t = threadIdx.x;
    int v = (t < NBLK) ? g_bsum[t] : 0;
    sh[t] = v;
    __syncthreads();
    for (int o = 1; o < SCAN_B; o <<= 1) {
        int u = (t >= o) ? sh[t - o] : 0;
        __syncthreads();
        sh[t] += u;
        __syncthreads();
    }
    if (t < NBLK) g_boff[t] = sh[t] - v;   // exclusive
}

__global__ void offsets_kernel() {
    __shared__ int ws[8];
    int t = threadIdx.x, lane = t & 31, w = t >> 5;
    int i = blockIdx.x * SCAN_B + t;
    int v = (i < NN) ? g_deg[i] : 0;
    int s = v;
#pragma unroll
    for (int o = 1; o < 32; o <<= 1) {
        int u = __shfl_up_sync(0xffffffffu, s, o);
        if (lane >= o) s += u;
    }
    if (lane == 31) ws[w] = s;
    __syncthreads();
    if (t < 8) {
        int a = ws[t];
#pragma unroll
        for (int o = 1; o < 8; o <<= 1) {
            int u = __shfl_up_sync(0xffu, a, o);
            if (t >= o) a += u;
        }
        ws[t] = a;
    }
    __syncthreads();
    int ex = s - v + (w ? ws[w - 1] : 0) + g_boff[blockIdx.x];
    if (i < NN) { g_off[i] = ex; g_cur[i] = ex; }
}

__global__ void scatter_kernel(const int* __restrict__ src,
                               const int* __restrict__ dst,
                               const int* __restrict__ ea) {
    int e = blockIdx.x * blockDim.x + threadIdx.x;
    if (e >= EE) return;
    int d = dst[e];
    int code = (ea[e * 3 + 0] * 5 + ea[e * 3 + 1]) * 5 + ea[e * 3 + 2];
    int pos = atomicAdd(&g_cur[d], 1);
    g_csr[pos] = (src[e] << 7) | code;   // src < 2^16, code < 2^7
}

// ---------------------------------------------------------------------------
// Aggregation: one warp per dst node. fp16 gather, packed CSR, fp32 math.
// ---------------------------------------------------------------------------
__device__ __forceinline__ void acc_edge(float4& acc, int p, int lane,
                                         const float4* cb4) {
    int s    = p >> 7;
    int code = p & 127;
    uint2 xv = g_xh[s * 32 + lane];
    float2 lo = __half22float2(*(__half2*)&xv.x);
    float2 hi = __half22float2(*(__half2*)&xv.y);
    float4 ca = cb4[code * 32 + lane];
    acc.x += fmaxf(lo.x + ca.x, 0.f);
    acc.y += fmaxf(lo.y + ca.y, 0.f);
    acc.z += fmaxf(hi.x + ca.z, 0.f);
    acc.w += fmaxf(hi.y + ca.w, 0.f);
}

__global__ void agg_kernel(const float4* __restrict__ x4,
                           const float*  __restrict__ eps) {
    int gt = blockIdx.x * blockDim.x + threadIdx.x;
    int v = gt >> 5;
    if (v >= NN) return;
    int lane = gt & 31;

    const float4* cb4 = (const float4*)g_combo;
    int start = g_off[v];
    int deg   = g_deg[v];

    float4 acc = make_float4(0, 0, 0, 0);
    int i = 0;
    for (; i + 4 <= deg; i += 4) {
        int a = g_csr[start + i];
        int b = g_csr[start + i + 1];
        int c = g_csr[start + i + 2];
        int d = g_csr[start + i + 3];
        acc_edge(acc, a, lane, cb4);
        acc_edge(acc, b, lane, cb4);
        acc_edge(acc, c, lane, cb4);
        acc_edge(acc, d, lane, cb4);
    }
    for (; i < deg; i++) acc_edge(acc, g_csr[start + i], lane, cb4);

    float c = 1.0f + *eps;
    float4 xv = x4[v * 32 + lane];
    float4 h;
    h.x = fmaf(c, xv.x, acc.x);
    h.y = fmaf(c, xv.y, acc.y);
    h.z = fmaf(c, xv.z, acc.z);
    h.w = fmaf(c, xv.w, acc.w);
    g_h[v * 32 + lane] = h;
}

// ---------------------------------------------------------------------------
// GEMM via fma.rn.f32x2, even/odd-k packed accumulators (unchanged).
// ---------------------------------------------------------------------------
#define WT_PITCH 132
#define WT_FLOATS (128 * WT_PITCH)
#define XS_OFF_B  (WT_FLOATS * 4)
#define GEMM_SMEM (XS_OFF_B + 64 * 128 * 4)

__device__ __forceinline__ float2 unpk(unsigned long long v) {
    float2 r;
    asm("mov.b64 {%0, %1}, %2;" : "=f"(r.x), "=f"(r.y) : "l"(v));
    return r;
}

template <int PASS>
__global__ __launch_bounds__(128)
void gemm_kernel(const float* __restrict__ Wg,
                 const float* __restrict__ bias,
                 float*       __restrict__ outp,
                 const float* __restrict__ gamma,
                 const float* __restrict__ beta) {
    extern __shared__ float sh[];
    __shared__ __align__(16) float ssum[128];
    __shared__ __align__(16) float ssq[128];
    __shared__ __align__(16) float sa[128];
    __shared__ __align__(16) float sb[128];

    const int t    = threadIdx.x;
    const int lane = t & 31;
    const int wrp  = t >> 5;

    if (PASS == 1) { ssum[t] = 0.f; ssq[t] = 0.f; }
    if (PASS == 2) {
        const float inv = 1.0f / (float)NN;
        float mean = g_sum[t] * inv;
        float var  = g_sumsq[t] * inv - mean * mean;
        float s = gamma[t] * rsqrtf(var + 1e-5f);
        sa[t] = s;
        sb[t] = beta[t] - mean * s;
    }
    __syncthreads();

    // Stage W transposed: Wt[c][k] = W[k][c], pitch 132
    {
        const int c = t;
        for (int g = 0; g < 32; g++) {
            int k0 = g * 4;
            float w0 = Wg[(k0 + 0) * 128 + c];
            float w1 = Wg[(k0 + 1) * 128 + c];
            float w2 = Wg[(k0 + 2) * 128 + c];
            float w3 = Wg[(k0 + 3) * 128 + c];
            *(float4*)&sh[c * WT_PITCH + k0] = make_float4(w0, w1, w2, w3);
        }
    }

    const float4* in4 = (PASS == 1) ? (const float4*)g_h : (const float4*)g_h1;
    float* xs = sh + WT_FLOATS;
    const int rowbase = blockIdx.x * 64;
#pragma unroll
    for (int j = 0; j < 16; j++) {
        int p = t + j * 128;
        int row = p >> 5, cp = p & 31;
        int gr = rowbase + row;
        float4 v = make_float4(0, 0, 0, 0);
        if (gr < NN) v = in4[gr * 32 + cp];
        if (PASS == 2) {
            float4 a = *(const float4*)&sa[cp * 4];
            float4 b = *(const float4*)&sb[cp * 4];
            v.x = fmaxf(fmaf(v.x, a.x, b.x), 0.f);
            v.y = fmaxf(fmaf(v.y, a.y, b.y), 0.f);
            v.z = fmaxf(fmaf(v.z, a.z, b.z), 0.f);
            v.w = fmaxf(fmaf(v.w, a.w, b.w), 0.f);
        }
        *(float4*)&xs[row * 128 + cp * 4] = v;
    }
    __syncthreads();

    float* out_f = (PASS == 1) ? (float*)g_h1 : outp;

    float bv[4];
#pragma unroll
    for (int cc = 0; cc < 4; cc++) bv[cc] = bias[lane + 32 * cc];

    const unsigned shb = (unsigned)__cvta_generic_to_shared(sh);
    unsigned wb[4];
#pragma unroll
    for (int cc = 0; cc < 4; cc++) wb[cc] = shb + (unsigned)((lane + 32 * cc) * WT_PITCH) * 4u;
    const unsigned xsb = shb + XS_OFF_B;

    float ts[4] = {0, 0, 0, 0};
    float tq[4] = {0, 0, 0, 0};

    for (int half = 0; half < 2; half++) {
        const int r0 = half * 32 + wrp * 8;
        unsigned xr[8];
#pragma unroll
        for (int r = 0; r < 8; r++) xr[r] = xsb + (unsigned)((r0 + r) * 128) * 4u;

        unsigned long long acc[8][4];
#pragma unroll
        for (int r = 0; r < 8; r++)
#pragma unroll
            for (int cc = 0; cc < 4; cc++) acc[r][cc] = 0ULL;

#pragma unroll 4
        for (int k = 0; k < 128; k += 4) {
            unsigned long long w01[4], w23[4];
#pragma unroll
            for (int cc = 0; cc < 4; cc++)
                asm("ld.shared.v2.b64 {%0, %1}, [%2];"
                    : "=l"(w01[cc]), "=l"(w23[cc]) : "r"(wb[cc] + (unsigned)(k * 4)));
#pragma unroll
            for (int r = 0; r < 8; r++) {
                unsigned long long x01, x23;
                asm("ld.shared.v2.b64 {%0, %1}, [%2];"
                    : "=l"(x01), "=l"(x23) : "r"(xr[r] + (unsigned)(k * 4)));
#pragma unroll
                for (int cc = 0; cc < 4; cc++) {
                    asm("fma.rn.f32x2 %0, %1, %2, %0;" : "+l"(acc[r][cc]) : "l"(x01), "l"(w01[cc]));
                    asm("fma.rn.f32x2 %0, %1, %2, %0;" : "+l"(acc[r][cc]) : "l"(x23), "l"(w23[cc]));
                }
            }
        }

#pragma unroll
        for (int r = 0; r < 8; r++) {
            int gr = rowbase + r0 + r;
            if (gr < NN) {
#pragma unroll
                for (int cc = 0; cc < 4; cc++) {
                    float2 p = unpk(acc[r][cc]);
                    float o = p.x + p.y + bv[cc];
                    out_f[gr * 128 + lane + 32 * cc] = o;
                    if (PASS == 1) { ts[cc] += o; tq[cc] += o * o; }
                }
            }
        }
    }

    if (PASS == 1) {
#pragma unroll
        for (int cc = 0; cc < 4; cc++) {
            atomicAdd(&ssum[lane + 32 * cc], ts[cc]);
            atomicAdd(&ssq [lane + 32 * cc], tq[cc]);
        }
        __syncthreads();
        atomicAdd(&g_sum[t],   ssum[t]);
        atomicAdd(&g_sumsq[t], ssq[t]);
    }
}

// ---------------------------------------------------------------------------
extern "C" void kernel_launch(void* const* d_in, const int* in_sizes, int n_in,
                              void* d_out, int out_size) {
    const float* x     = (const float*)d_in[0];
    const int*   ea    = (const int*)  d_in[1];
    const int*   src   = (const int*)  d_in[2];
    const int*   dst   = (const int*)  d_in[3];
    const float* bond  = (const float*)d_in[4];
    const float* eps   = (const float*)d_in[5];
    const float* W1    = (const float*)d_in[6];
    const float* b1    = (const float*)d_in[7];
    const float* gamma = (const float*)d_in[8];
    const float* beta  = (const float*)d_in[9];
    const float* W2    = (const float*)d_in[10];
    const float* b2    = (const float*)d_in[11];

    cudaFuncSetAttribute(gemm_kernel<1>, cudaFuncAttributeMaxDynamicSharedMemorySize, GEMM_SMEM);
    cudaFuncSetAttribute(gemm_kernel<2>, cudaFuncAttributeMaxDynamicSharedMemorySize, GEMM_SMEM);

    setup_kernel<<<(NN * 32 + 255) / 256, 256>>>((const float4*)x);
    combo_kernel<<<125, 128>>>(bond);
    hist_kernel<<<(EE + 255) / 256, 256>>>(dst);
    blocksum_kernel<<<NBLK, SCAN_B>>>();
    bscan_kernel<<<1, SCAN_B>>>();
    offsets_kernel<<<NBLK, SCAN_B>>>();
    scatter_kernel<<<(EE + 255) / 256, 256>>>(src, dst, ea);
    agg_kernel<<<(NN * 32 + 255) / 256, 256>>>((const float4*)x, eps);
    gemm_kernel<1><<<(NN + 63) / 64, 128, GEMM_SMEM>>>(W1, b1, nullptr, nullptr, nullptr);
    gemm_kernel<2><<<(NN + 63) / 64, 128, GEMM_SMEM>>>(W2, b2, (float*)d_out, gamma, beta);
}